// round 12
// baseline (speedup 1.0000x reference)
#include <cuda_runtime.h>
#include <cuda_fp16.h>
#include <stdint.h>

// ============================================================================
// FibonacciKAN via monomial re-expansion, legacy mma.sync path (tcgen05 is
// unavailable: harness PTX targets compute_103, 'a'-gated ops rejected).
//   Y[32768,256] = A[32768,1024] @ W[1024,256] + bias, A = powers of tanh(x)
// R11: fp16-accumulate MMA experiment. Tensor pinned at 44-46% across every
// config -> hypothesis: fp32-accum HMMA is the half-rate legacy path. Chain 4
// MMAs per BK=64 tile in fp16 accumulators, promote to fp32 once per tile.
// launch_bounds(128,3) to give the +32 f16-acc regs headroom (R7 spill lesson).
// ============================================================================

#define B_ROWS 32768
#define IN_DIM 256
#define OUT_DIM 256
#define KDIM 1024
#define BM 64                 // rows per CTA
#define BN 128                // cols per CTA
#define BK 64
#define NKT (KDIM / BK)       // 16
#define NTHREADS 128

#define SA 72                 // row stride in halves (144 B) -> conflict-free LDSM
#define SWROW 72
#define ABYTES (BM * SA * 2)      // 9216
#define WBYTES (BN * SWROW * 2)   // 18432
#define SM_A0 0
#define SM_A1 (SM_A0 + ABYTES)
#define SM_W0 (SM_A1 + ABYTES)
#define SM_W1 (SM_W0 + WBYTES)
#define SM_TOTAL (SM_W1 + WBYTES)   // 55296 bytes/CTA -> 3 CTAs/SM (166KB)

__device__ __half g_W[OUT_DIM * KDIM];   // [o][k], k-contiguous
__device__ float  g_bias[OUT_DIM];

// ---------------------------------------------------------------------------
__device__ __forceinline__ uint32_t smem_u32(const void* p) {
    uint32_t a;
    asm("{ .reg .u64 t; cvta.to.shared.u64 t, %1; cvt.u32.u64 %0, t; }"
        : "=r"(a) : "l"(p));
    return a;
}
__device__ __forceinline__ void cp_async16(uint32_t dst, const void* src) {
    asm volatile("cp.async.cg.shared.global [%0], [%1], 16;"
                 :: "r"(dst), "l"(src) : "memory");
}
__device__ __forceinline__ void cp_commit() {
    asm volatile("cp.async.commit_group;" ::: "memory");
}
__device__ __forceinline__ void cp_wait0() {
    asm volatile("cp.async.wait_group 0;" ::: "memory");
}
__device__ __forceinline__ void ldsm_x4(uint32_t& r0, uint32_t& r1,
                                        uint32_t& r2, uint32_t& r3, uint32_t addr) {
    asm volatile("ldmatrix.sync.aligned.m8n8.x4.shared.b16 {%0,%1,%2,%3}, [%4];"
                 : "=r"(r0), "=r"(r1), "=r"(r2), "=r"(r3) : "r"(addr));
}
__device__ __forceinline__ uint32_t pack_h2(float a, float b) {
    __half2 h = __floats2half2_rn(a, b);
    return *(uint32_t*)&h;
}
__device__ __forceinline__ float tanh_fast(float x) {
    float y;
    asm("tanh.approx.f32 %0, %1;" : "=f"(y) : "f"(x));
    return y;
}

// ---------------------------------------------------------------------------
// Weight prep: C[i][o][d] -> monomial W[o][k=i*4+p] fp16 + bias[o]
// ---------------------------------------------------------------------------
__global__ void prep_weights_kernel(const float* __restrict__ C) {
    int o = blockIdx.x;
    int i = threadIdx.x;
    const float* c = C + ((size_t)i * OUT_DIM + o) * 6;
    float c1 = c[1], c2 = c[2], c3 = c[3], c4 = c[4], c5 = c[5];
    __half2* dst = (__half2*)(g_W + (size_t)o * KDIM + i * 4);
    dst[0] = __floats2half2_rn(c2 + 2.0f * c4, c3 + 3.0f * c5);
    dst[1] = __floats2half2_rn(c4, c5);

    float v = c1 + c3 + c5;
    #pragma unroll
    for (int s = 16; s > 0; s >>= 1)
        v += __shfl_xor_sync(0xFFFFFFFF, v, s);
    __shared__ float sb[8];
    if ((i & 31) == 0) sb[i >> 5] = v;
    __syncthreads();
    if (i < 8) {
        float w = sb[i];
        #pragma unroll
        for (int s = 4; s > 0; s >>= 1)
            w += __shfl_xor_sync(0xFF, w, s);
        if (i == 0) g_bias[o] = w;
    }
}

// ---------------------------------------------------------------------------
// Fused GEMM: 64x128 CTA, 4 warps of 32x64, 3 CTAs/SM, f16-accum MMA chains
// ---------------------------------------------------------------------------
__global__ __launch_bounds__(NTHREADS, 3)
void kan_gemm_kernel(const float* __restrict__ X, float* __restrict__ Y) {
    extern __shared__ char smem[];
    const uint32_t sbase = smem_u32(smem);
    const int tid  = threadIdx.x;
    const int warp = tid >> 5;          // 0..3
    const int lane = tid & 31;
    const int wr = warp >> 1;           // 0..1 (32-row warp tiles)
    const int wc = warp & 1;            // 0..1 (64-col warp tiles)
    const int g  = lane >> 2;
    const int tig = lane & 3;
    const int rowbase = (int)(blockIdx.x >> 1) * BM;
    const int colbase = (int)(blockIdx.x & 1) * BN;

    // W staging geometry: 1024 16B chunks, 8 per thread
    const int wrow0 = tid >> 3;         // 0..15 (+16 per j)
    const int wseg  = tid & 7;          // 0..7

    // ldmatrix per-thread base offsets (bytes)
    const uint32_t a_lds = (uint32_t)(wr * 32 + (lane & 7) + ((lane >> 3) & 1) * 8)
                           * (SA * 2) + ((lane >> 4) & 1) * 16;
    const uint32_t b_lds = (uint32_t)(wc * 64 + (lane & 7) + ((lane >> 4) & 1) * 8)
                           * (SWROW * 2) + ((lane >> 3) & 1) * 16;

    float acc[2][8][4];
    #pragma unroll
    for (int mt = 0; mt < 2; ++mt)
        #pragma unroll
        for (int nt = 0; nt < 8; ++nt)
            #pragma unroll
            for (int q = 0; q < 4; ++q) acc[mt][nt][q] = 0.0f;

    // ---- prologue: stage tile 0 into buffer 0 ----
    {
        #pragma unroll
        for (int j = 0; j < 8; ++j) {
            int nrow = wrow0 + j * 16;                 // 0..127 (CTA-local col)
            cp_async16(sbase + SM_W0 + (uint32_t)nrow * (SWROW * 2) + wseg * 16,
                       g_W + (size_t)(colbase + nrow) * KDIM + wseg * 8);
        }
        cp_commit();
        #pragma unroll
        for (int j = 0; j < 2; ++j) {
            int e = tid + j * NTHREADS;                // 0..255
            int r = e >> 2;                            // 0..63
            int grp = e & 3;
            float4 xv = *(const float4*)(X + (size_t)(rowbase + r) * IN_DIM + grp * 4);
            float t0 = tanh_fast(xv.x), t1 = tanh_fast(xv.y);
            float t2 = tanh_fast(xv.z), t3 = tanh_fast(xv.w);
            float s0 = t0*t0, s1 = t1*t1, s2 = t2*t2, s3 = t3*t3;
            uint4 c01, c23;
            c01.x = pack_h2(t0, s0); c01.y = pack_h2(s0*t0, s0*s0);
            c01.z = pack_h2(t1, s1); c01.w = pack_h2(s1*t1, s1*s1);
            c23.x = pack_h2(t2, s2); c23.y = pack_h2(s2*t2, s2*s2);
            c23.z = pack_h2(t3, s3); c23.w = pack_h2(s3*t3, s3*s3);
            uint32_t off = (uint32_t)r * (SA * 2) + (uint32_t)grp * 32;
            *(uint4*)(smem + SM_A0 + off)      = c01;
            *(uint4*)(smem + SM_A0 + off + 16) = c23;
        }
    }

    for (int kt = 0; kt < NKT; ++kt) {
        const int cur = kt & 1;
        const uint32_t Ab  = sbase + (cur ? SM_A1 : SM_A0);
        const uint32_t Wb  = sbase + (cur ? SM_W1 : SM_W0);
        const uint32_t Abn = sbase + (cur ? SM_A0 : SM_A1);
        const uint32_t Wbn = sbase + (cur ? SM_W0 : SM_W1);

        // X prefetch for next tile (2 slots per thread)
        float4 xv0, xv1;
        if (kt + 1 < NKT) {
            int e0 = tid, e1 = tid + NTHREADS;
            xv0 = *(const float4*)(X + (size_t)(rowbase + (e0 >> 2)) * IN_DIM
                                   + (kt + 1) * 16 + (e0 & 3) * 4);
            xv1 = *(const float4*)(X + (size_t)(rowbase + (e1 >> 2)) * IN_DIM
                                   + (kt + 1) * 16 + (e1 & 3) * 4);
        }

        cp_wait0();
        __syncthreads();

        // issue cp.async for W tile kt+1
        if (kt + 1 < NKT) {
            #pragma unroll
            for (int j = 0; j < 8; ++j) {
                int nrow = wrow0 + j * 16;
                cp_async16(Wbn + (uint32_t)nrow * (SWROW * 2) + wseg * 16,
                           g_W + (size_t)(colbase + nrow) * KDIM + (kt + 1) * BK + wseg * 8);
            }
            cp_commit();
        }

        // ---- MMAs on tile kt: 4 k-steps chained in fp16 accumulators ----
        uint32_t hacc[2][8][2];
        #pragma unroll
        for (int mt = 0; mt < 2; ++mt)
            #pragma unroll
            for (int nt = 0; nt < 8; ++nt) {
                hacc[mt][nt][0] = 0u;
                hacc[mt][nt][1] = 0u;
            }

        #pragma unroll
        for (int kk = 0; kk < 4; ++kk) {
            uint32_t a[2][4];
            #pragma unroll
            for (int mt = 0; mt < 2; ++mt)
                ldsm_x4(a[mt][0], a[mt][1], a[mt][2], a[mt][3],
                        Ab + a_lds + mt * 16 * (SA * 2) + kk * 32);
            #pragma unroll
            for (int ntp = 0; ntp < 4; ++ntp) {
                uint32_t b[4];
                ldsm_x4(b[0], b[1], b[2], b[3],
                        Wb + b_lds + ntp * 16 * (SWROW * 2) + kk * 32);
                #pragma unroll
                for (int h = 0; h < 2; ++h) {
                    const int nt = ntp * 2 + h;
                    #pragma unroll
                    for (int mt = 0; mt < 2; ++mt) {
                        asm volatile(
                            "mma.sync.aligned.m16n8k16.row.col.f16.f16.f16.f16 "
                            "{%0,%1}, {%2,%3,%4,%5}, {%6,%7}, {%0,%1};\n"
                            : "+r"(hacc[mt][nt][0]), "+r"(hacc[mt][nt][1])
                            : "r"(a[mt][0]), "r"(a[mt][1]), "r"(a[mt][2]), "r"(a[mt][3]),
                              "r"(b[h * 2]), "r"(b[h * 2 + 1]));
                    }
                }
            }
        }

        // ---- promote chunk (K=64) into fp32 accumulators ----
        #pragma unroll
        for (int mt = 0; mt < 2; ++mt)
            #pragma unroll
            for (int nt = 0; nt < 8; ++nt) {
                float2 lo = __half22float2(*(const __half2*)&hacc[mt][nt][0]);
                float2 hi = __half22float2(*(const __half2*)&hacc[mt][nt][1]);
                acc[mt][nt][0] += lo.x;
                acc[mt][nt][1] += lo.y;
                acc[mt][nt][2] += hi.x;
                acc[mt][nt][3] += hi.y;
            }

        // ---- stage A tile kt+1 ----
        if (kt + 1 < NKT) {
            #pragma unroll
            for (int j = 0; j < 2; ++j) {
                float4 xv = j ? xv1 : xv0;
                int e = tid + j * NTHREADS;
                int r = e >> 2;
                int grp = e & 3;
                float t0 = tanh_fast(xv.x), t1 = tanh_fast(xv.y);
                float t2 = tanh_fast(xv.z), t3 = tanh_fast(xv.w);
                float s0 = t0*t0, s1 = t1*t1, s2 = t2*t2, s3 = t3*t3;
                uint4 c01, c23;
                c01.x = pack_h2(t0, s0); c01.y = pack_h2(s0*t0, s0*s0);
                c01.z = pack_h2(t1, s1); c01.w = pack_h2(s1*t1, s1*s1);
                c23.x = pack_h2(t2, s2); c23.y = pack_h2(s2*t2, s2*s2);
                c23.z = pack_h2(t3, s3); c23.w = pack_h2(s3*t3, s3*s3);
                uint32_t off = (uint32_t)r * (SA * 2) + (uint32_t)grp * 32;
                *(uint4*)((char*)smem + (Abn - sbase) + off)      = c01;
                *(uint4*)((char*)smem + (Abn - sbase) + off + 16) = c23;
            }
        }
    }

    // ---- epilogue: + bias, fp32 store ----
    #pragma unroll
    for (int mt = 0; mt < 2; ++mt) {
        int r0 = rowbase + wr * 32 + mt * 16;
        #pragma unroll
        for (int nt = 0; nt < 8; ++nt) {
            int c0 = colbase + wc * 64 + nt * 8 + tig * 2;
            float b0 = __ldg(&g_bias[c0]);
            float b1 = __ldg(&g_bias[c0 + 1]);
            int r = r0 + g;
            float2 lo = make_float2(acc[mt][nt][0] + b0, acc[mt][nt][1] + b1);
            float2 hi = make_float2(acc[mt][nt][2] + b0, acc[mt][nt][3] + b1);
            *(float2*)(Y + (size_t)r * OUT_DIM + c0)       = lo;
            *(float2*)(Y + (size_t)(r + 8) * OUT_DIM + c0) = hi;
        }
    }
}

// ---------------------------------------------------------------------------
extern "C" void kernel_launch(void* const* d_in, const int* in_sizes, int n_in,
                              void* d_out, int out_size) {
    const float* x = (const float*)d_in[0];
    const float* coeffs = (const float*)d_in[1];
    if (n_in >= 2 && in_sizes[0] == OUT_DIM * IN_DIM * 6) {
        coeffs = (const float*)d_in[0];
        x = (const float*)d_in[1];
    }
    float* y = (float*)d_out;

    static bool attr_set = false;
    if (!attr_set) {
        cudaFuncSetAttribute(kan_gemm_kernel,
                             cudaFuncAttributeMaxDynamicSharedMemorySize, SM_TOTAL);
        attr_set = true;
    }

    prep_weights_kernel<<<OUT_DIM, IN_DIM>>>(coeffs);
    kan_gemm_kernel<<<(B_ROWS / BM) * (OUT_DIM / BN), NTHREADS, SM_TOTAL>>>(x, y);
}

// round 13
// speedup vs baseline: 1.0700x; 1.0700x over previous
#include <cuda_runtime.h>
#include <cuda_fp16.h>
#include <stdint.h>

// ============================================================================
// FibonacciKAN via monomial re-expansion, legacy mma.sync path (tcgen05 is
// unavailable: harness PTX targets compute_103, 'a'-gated ops rejected).
//   Y[32768,256] = A[32768,1024] @ W[1024,256] + bias, A = powers of tanh(x)
// R12: kk-level fragment double-buffering at launch_bounds(128,3) (170-reg
// budget -- the R7 pipelining idea, now with register headroom). LDSMs for
// step kk+1 issue before the MMAs of step kk, overlapping crossbar with
// tensor within each warp. fp32-accum MMA restored (R11 falsified fp16-acc).
// ============================================================================

#define B_ROWS 32768
#define IN_DIM 256
#define OUT_DIM 256
#define KDIM 1024
#define BM 64                 // rows per CTA
#define BN 128                // cols per CTA
#define BK 64
#define NKT (KDIM / BK)       // 16
#define NTHREADS 128

#define SA 72                 // row stride in halves (144 B) -> conflict-free LDSM
#define SWROW 72
#define ABYTES (BM * SA * 2)      // 9216
#define WBYTES (BN * SWROW * 2)   // 18432
#define SM_A0 0
#define SM_A1 (SM_A0 + ABYTES)
#define SM_W0 (SM_A1 + ABYTES)
#define SM_W1 (SM_W0 + WBYTES)
#define SM_TOTAL (SM_W1 + WBYTES)   // 55296 bytes/CTA

__device__ __half g_W[OUT_DIM * KDIM];   // [o][k], k-contiguous
__device__ float  g_bias[OUT_DIM];

// ---------------------------------------------------------------------------
__device__ __forceinline__ uint32_t smem_u32(const void* p) {
    uint32_t a;
    asm("{ .reg .u64 t; cvta.to.shared.u64 t, %1; cvt.u32.u64 %0, t; }"
        : "=r"(a) : "l"(p));
    return a;
}
__device__ __forceinline__ void cp_async16(uint32_t dst, const void* src) {
    asm volatile("cp.async.cg.shared.global [%0], [%1], 16;"
                 :: "r"(dst), "l"(src) : "memory");
}
__device__ __forceinline__ void cp_commit() {
    asm volatile("cp.async.commit_group;" ::: "memory");
}
__device__ __forceinline__ void cp_wait0() {
    asm volatile("cp.async.wait_group 0;" ::: "memory");
}
__device__ __forceinline__ void ldsm_x4(uint32_t& r0, uint32_t& r1,
                                        uint32_t& r2, uint32_t& r3, uint32_t addr) {
    asm volatile("ldmatrix.sync.aligned.m8n8.x4.shared.b16 {%0,%1,%2,%3}, [%4];"
                 : "=r"(r0), "=r"(r1), "=r"(r2), "=r"(r3) : "r"(addr));
}
__device__ __forceinline__ uint32_t pack_h2(float a, float b) {
    __half2 h = __floats2half2_rn(a, b);
    return *(uint32_t*)&h;
}
__device__ __forceinline__ float tanh_fast(float x) {
    float y;
    asm("tanh.approx.f32 %0, %1;" : "=f"(y) : "f"(x));
    return y;
}

// ---------------------------------------------------------------------------
// Weight prep: C[i][o][d] -> monomial W[o][k=i*4+p] fp16 + bias[o]
// ---------------------------------------------------------------------------
__global__ void prep_weights_kernel(const float* __restrict__ C) {
    int o = blockIdx.x;
    int i = threadIdx.x;
    const float* c = C + ((size_t)i * OUT_DIM + o) * 6;
    float c1 = c[1], c2 = c[2], c3 = c[3], c4 = c[4], c5 = c[5];
    __half2* dst = (__half2*)(g_W + (size_t)o * KDIM + i * 4);
    dst[0] = __floats2half2_rn(c2 + 2.0f * c4, c3 + 3.0f * c5);
    dst[1] = __floats2half2_rn(c4, c5);

    float v = c1 + c3 + c5;
    #pragma unroll
    for (int s = 16; s > 0; s >>= 1)
        v += __shfl_xor_sync(0xFFFFFFFF, v, s);
    __shared__ float sb[8];
    if ((i & 31) == 0) sb[i >> 5] = v;
    __syncthreads();
    if (i < 8) {
        float w = sb[i];
        #pragma unroll
        for (int s = 4; s > 0; s >>= 1)
            w += __shfl_xor_sync(0xFF, w, s);
        if (i == 0) g_bias[o] = w;
    }
}

// ---------------------------------------------------------------------------
// Fused GEMM: 64x128 CTA, 4 warps of 32x64, 3 CTAs/SM, frag double-buffering
// ---------------------------------------------------------------------------
__global__ __launch_bounds__(NTHREADS, 3)
void kan_gemm_kernel(const float* __restrict__ X, float* __restrict__ Y) {
    extern __shared__ char smem[];
    const uint32_t sbase = smem_u32(smem);
    const int tid  = threadIdx.x;
    const int warp = tid >> 5;          // 0..3
    const int lane = tid & 31;
    const int wr = warp >> 1;           // 0..1 (32-row warp tiles)
    const int wc = warp & 1;            // 0..1 (64-col warp tiles)
    const int g  = lane >> 2;
    const int tig = lane & 3;
    const int rowbase = (int)(blockIdx.x >> 1) * BM;
    const int colbase = (int)(blockIdx.x & 1) * BN;

    // W staging geometry: 1024 16B chunks, 8 per thread
    const int wrow0 = tid >> 3;         // 0..15 (+16 per j)
    const int wseg  = tid & 7;          // 0..7

    // ldmatrix per-thread base offsets (bytes)
    const uint32_t a_lds = (uint32_t)(wr * 32 + (lane & 7) + ((lane >> 3) & 1) * 8)
                           * (SA * 2) + ((lane >> 4) & 1) * 16;
    const uint32_t b_lds = (uint32_t)(wc * 64 + (lane & 7) + ((lane >> 4) & 1) * 8)
                           * (SWROW * 2) + ((lane >> 3) & 1) * 16;

    float acc[2][8][4];
    #pragma unroll
    for (int mt = 0; mt < 2; ++mt)
        #pragma unroll
        for (int nt = 0; nt < 8; ++nt)
            #pragma unroll
            for (int q = 0; q < 4; ++q) acc[mt][nt][q] = 0.0f;

    // ---- prologue: stage tile 0 into buffer 0 ----
    {
        #pragma unroll
        for (int j = 0; j < 8; ++j) {
            int nrow = wrow0 + j * 16;                 // 0..127 (CTA-local col)
            cp_async16(sbase + SM_W0 + (uint32_t)nrow * (SWROW * 2) + wseg * 16,
                       g_W + (size_t)(colbase + nrow) * KDIM + wseg * 8);
        }
        cp_commit();
        #pragma unroll
        for (int j = 0; j < 2; ++j) {
            int e = tid + j * NTHREADS;                // 0..255
            int r = e >> 2;                            // 0..63
            int grp = e & 3;
            float4 xv = *(const float4*)(X + (size_t)(rowbase + r) * IN_DIM + grp * 4);
            float t0 = tanh_fast(xv.x), t1 = tanh_fast(xv.y);
            float t2 = tanh_fast(xv.z), t3 = tanh_fast(xv.w);
            float s0 = t0*t0, s1 = t1*t1, s2 = t2*t2, s3 = t3*t3;
            uint4 c01, c23;
            c01.x = pack_h2(t0, s0); c01.y = pack_h2(s0*t0, s0*s0);
            c01.z = pack_h2(t1, s1); c01.w = pack_h2(s1*t1, s1*s1);
            c23.x = pack_h2(t2, s2); c23.y = pack_h2(s2*t2, s2*s2);
            c23.z = pack_h2(t3, s3); c23.w = pack_h2(s3*t3, s3*s3);
            uint32_t off = (uint32_t)r * (SA * 2) + (uint32_t)grp * 32;
            *(uint4*)(smem + SM_A0 + off)      = c01;
            *(uint4*)(smem + SM_A0 + off + 16) = c23;
        }
    }

    for (int kt = 0; kt < NKT; ++kt) {
        const int cur = kt & 1;
        const uint32_t Ab  = sbase + (cur ? SM_A1 : SM_A0);
        const uint32_t Wb  = sbase + (cur ? SM_W1 : SM_W0);
        const uint32_t Abn = sbase + (cur ? SM_A0 : SM_A1);
        const uint32_t Wbn = sbase + (cur ? SM_W0 : SM_W1);

        // X prefetch for next tile (2 slots per thread)
        float4 xv0, xv1;
        if (kt + 1 < NKT) {
            int e0 = tid, e1 = tid + NTHREADS;
            xv0 = *(const float4*)(X + (size_t)(rowbase + (e0 >> 2)) * IN_DIM
                                   + (kt + 1) * 16 + (e0 & 3) * 4);
            xv1 = *(const float4*)(X + (size_t)(rowbase + (e1 >> 2)) * IN_DIM
                                   + (kt + 1) * 16 + (e1 & 3) * 4);
        }

        cp_wait0();
        __syncthreads();

        // issue cp.async for W tile kt+1
        if (kt + 1 < NKT) {
            #pragma unroll
            for (int j = 0; j < 8; ++j) {
                int nrow = wrow0 + j * 16;
                cp_async16(Wbn + (uint32_t)nrow * (SWROW * 2) + wseg * 16,
                           g_W + (size_t)(colbase + nrow) * KDIM + (kt + 1) * BK + wseg * 8);
            }
            cp_commit();
        }

        // ---- MMAs on tile kt: 4 kk-steps, fragments double-buffered so the
        //      LDSMs of step kk+1 overlap the 16 MMAs of step kk ----
        uint32_t fa[2][2][4];   // [set][mt][reg]
        uint32_t fb[2][4][4];   // [set][ntp][reg]

        #pragma unroll
        for (int mt = 0; mt < 2; ++mt)
            ldsm_x4(fa[0][mt][0], fa[0][mt][1], fa[0][mt][2], fa[0][mt][3],
                    Ab + a_lds + mt * 16 * (SA * 2));
        #pragma unroll
        for (int ntp = 0; ntp < 4; ++ntp)
            ldsm_x4(fb[0][ntp][0], fb[0][ntp][1], fb[0][ntp][2], fb[0][ntp][3],
                    Wb + b_lds + ntp * 16 * (SWROW * 2));

        #pragma unroll
        for (int kk = 0; kk < 4; ++kk) {
            const int cs = kk & 1;
            const int ns = cs ^ 1;
            if (kk < 3) {
                #pragma unroll
                for (int mt = 0; mt < 2; ++mt)
                    ldsm_x4(fa[ns][mt][0], fa[ns][mt][1], fa[ns][mt][2], fa[ns][mt][3],
                            Ab + a_lds + mt * 16 * (SA * 2) + (kk + 1) * 32);
                #pragma unroll
                for (int ntp = 0; ntp < 4; ++ntp)
                    ldsm_x4(fb[ns][ntp][0], fb[ns][ntp][1], fb[ns][ntp][2], fb[ns][ntp][3],
                            Wb + b_lds + ntp * 16 * (SWROW * 2) + (kk + 1) * 32);
            }
            #pragma unroll
            for (int ntp = 0; ntp < 4; ++ntp) {
                #pragma unroll
                for (int h = 0; h < 2; ++h) {
                    const int nt = ntp * 2 + h;
                    #pragma unroll
                    for (int mt = 0; mt < 2; ++mt) {
                        asm volatile(
                            "mma.sync.aligned.m16n8k16.row.col.f32.f16.f16.f32 "
                            "{%0,%1,%2,%3}, {%4,%5,%6,%7}, {%8,%9}, {%0,%1,%2,%3};\n"
                            : "+f"(acc[mt][nt][0]), "+f"(acc[mt][nt][1]),
                              "+f"(acc[mt][nt][2]), "+f"(acc[mt][nt][3])
                            : "r"(fa[cs][mt][0]), "r"(fa[cs][mt][1]),
                              "r"(fa[cs][mt][2]), "r"(fa[cs][mt][3]),
                              "r"(fb[cs][ntp][h * 2]), "r"(fb[cs][ntp][h * 2 + 1]));
                    }
                }
            }
        }

        // ---- stage A tile kt+1 ----
        if (kt + 1 < NKT) {
            #pragma unroll
            for (int j = 0; j < 2; ++j) {
                float4 xv = j ? xv1 : xv0;
                int e = tid + j * NTHREADS;
                int r = e >> 2;
                int grp = e & 3;
                float t0 = tanh_fast(xv.x), t1 = tanh_fast(xv.y);
                float t2 = tanh_fast(xv.z), t3 = tanh_fast(xv.w);
                float s0 = t0*t0, s1 = t1*t1, s2 = t2*t2, s3 = t3*t3;
                uint4 c01, c23;
                c01.x = pack_h2(t0, s0); c01.y = pack_h2(s0*t0, s0*s0);
                c01.z = pack_h2(t1, s1); c01.w = pack_h2(s1*t1, s1*s1);
                c23.x = pack_h2(t2, s2); c23.y = pack_h2(s2*t2, s2*s2);
                c23.z = pack_h2(t3, s3); c23.w = pack_h2(s3*t3, s3*s3);
                uint32_t off = (uint32_t)r * (SA * 2) + (uint32_t)grp * 32;
                *(uint4*)((char*)smem + (Abn - sbase) + off)      = c01;
                *(uint4*)((char*)smem + (Abn - sbase) + off + 16) = c23;
            }
        }
    }

    // ---- epilogue: + bias, fp32 store ----
    #pragma unroll
    for (int mt = 0; mt < 2; ++mt) {
        int r0 = rowbase + wr * 32 + mt * 16;
        #pragma unroll
        for (int nt = 0; nt < 8; ++nt) {
            int c0 = colbase + wc * 64 + nt * 8 + tig * 2;
            float b0 = __ldg(&g_bias[c0]);
            float b1 = __ldg(&g_bias[c0 + 1]);
            int r = r0 + g;
            float2 lo = make_float2(acc[mt][nt][0] + b0, acc[mt][nt][1] + b1);
            float2 hi = make_float2(acc[mt][nt][2] + b0, acc[mt][nt][3] + b1);
            *(float2*)(Y + (size_t)r * OUT_DIM + c0)       = lo;
            *(float2*)(Y + (size_t)(r + 8) * OUT_DIM + c0) = hi;
        }
    }
}

// ---------------------------------------------------------------------------
extern "C" void kernel_launch(void* const* d_in, const int* in_sizes, int n_in,
                              void* d_out, int out_size) {
    const float* x = (const float*)d_in[0];
    const float* coeffs = (const float*)d_in[1];
    if (n_in >= 2 && in_sizes[0] == OUT_DIM * IN_DIM * 6) {
        coeffs = (const float*)d_in[0];
        x = (const float*)d_in[1];
    }
    float* y = (float*)d_out;

    static bool attr_set = false;
    if (!attr_set) {
        cudaFuncSetAttribute(kan_gemm_kernel,
                             cudaFuncAttributeMaxDynamicSharedMemorySize, SM_TOTAL);
        attr_set = true;
    }

    prep_weights_kernel<<<OUT_DIM, IN_DIM>>>(coeffs);
    kan_gemm_kernel<<<(B_ROWS / BM) * (OUT_DIM / BN), NTHREADS, SM_TOTAL>>>(x, y);
}